// round 1
// baseline (speedup 1.0000x reference)
#include <cuda_runtime.h>
#include <cstdint>

// ---------------------------------------------------------------------------
// Problem constants
//   x: [B=256, T=512, I=300]  -> treat as A[M=131072, K=300], m = b*512 + t
//   xp = x @ Wcat^T + bcat    -> [M, 384]  (cols 0:192 fwd gates, 192:384 bwd)
//   GRU scan over T (fwd + bwd), only first/last hidden states survive
//   head: feat[256] -> 32 (LeakyReLU) -> 1
// ---------------------------------------------------------------------------

#define B_  256
#define T_  512
#define I_  300
#define H_  64
#define G3  192          // 3*H
#define NCAT 384         // 6*H
#define KPAD 304         // 300 padded to multiple of 8
#define M_  (B_ * T_)    // 131072

// Scratch (static device memory; no allocation allowed)
__device__ float g_WcatT[KPAD * NCAT];            // [k][n], zero-padded k>=300
__device__ float g_bcat[NCAT];
__device__ float g_xp[(size_t)M_ * NCAT];         // ~201 MB
__device__ float g_feat[B_ * 256];                // [b][ hf1 | hbF | hfF | hb1 ]

// ---------------------------------------------------------------------------
// f32x2 packed helpers (sm_100+)
// ---------------------------------------------------------------------------
__device__ __forceinline__ unsigned long long pack2(float lo, float hi) {
    unsigned long long r;
    asm("mov.b64 %0, {%1, %2};" : "=l"(r) : "f"(lo), "f"(hi));
    return r;
}
__device__ __forceinline__ unsigned long long fma2(unsigned long long a,
                                                   unsigned long long b,
                                                   unsigned long long c) {
    unsigned long long d;
    asm("fma.rn.f32x2 %0, %1, %2, %3;" : "=l"(d) : "l"(a), "l"(b), "l"(c));
    return d;
}
__device__ __forceinline__ float2 unpack2(unsigned long long v) {
    float lo, hi;
    asm("mov.b64 {%0, %1}, %2;" : "=f"(lo), "=f"(hi) : "l"(v));
    return make_float2(lo, hi);
}

__device__ __forceinline__ float sigmoidf_(float x) {
    return __fdividef(1.f, 1.f + __expf(-x));
}
__device__ __forceinline__ float tanhf_(float x) {
    return 1.f - __fdividef(2.f, 1.f + __expf(2.f * x));
}

// ---------------------------------------------------------------------------
// Kernel 0: build transposed+padded combined weight and bias
// ---------------------------------------------------------------------------
__global__ void prep_kernel(const float* __restrict__ Wif,
                            const float* __restrict__ Wib,
                            const float* __restrict__ bif,
                            const float* __restrict__ bib) {
    int i = blockIdx.x * blockDim.x + threadIdx.x;
    if (i < NCAT) g_bcat[i] = (i < G3) ? bif[i] : bib[i - G3];
    if (i < KPAD * NCAT) {
        int k = i / NCAT, n = i % NCAT;
        float v = 0.f;
        if (k < I_) v = (n < G3) ? Wif[n * I_ + k] : Wib[(n - G3) * I_ + k];
        g_WcatT[i] = v;
    }
}

// ---------------------------------------------------------------------------
// Kernel 1: SGEMM  C[M,384] = A[M,300] * WcatT + bcat   (f32x2 packed FFMA)
// BM=128, BN=128, BK=8, 256 threads, 8x8 microtile (stored as 8x4 f32x2)
// ---------------------------------------------------------------------------
__global__ __launch_bounds__(256, 2) void gemm_kernel(const float* __restrict__ A) {
    __shared__ float As[8][128];
    __shared__ float Bs[8][128];

    const int tid = threadIdx.x;
    const int m0 = blockIdx.x * 128;
    const int n0 = blockIdx.y * 128;

    const int ar = tid >> 1;             // 0..127 (A row within tile)
    const int ac4 = (tid & 1) * 4;       // 0 or 4 (A col group)
    const int br = tid >> 5;             // 0..7  (B row = k)
    const int bc = (tid & 31) * 4;       // B col group

    const int ty = tid >> 4;             // 0..15 -> rows ty*8
    const int tx = tid & 15;             // 0..15 -> cols tx*8

    const float* Arow = A + (size_t)(m0 + ar) * I_;

    unsigned long long acc2[8][4];
#pragma unroll
    for (int i = 0; i < 8; i++)
#pragma unroll
        for (int j = 0; j < 4; j++) acc2[i][j] = pack2(0.f, 0.f);

    for (int k0 = 0; k0 < KPAD; k0 += 8) {
        // --- load A tile (guarded at K edge; K%4==0 so float4 stays in-bounds)
        {
            int k = k0 + ac4;
            float4 av = make_float4(0.f, 0.f, 0.f, 0.f);
            if (k < I_) av = *(const float4*)(Arow + k);
            As[ac4 + 0][ar] = av.x;
            As[ac4 + 1][ar] = av.y;
            As[ac4 + 2][ar] = av.z;
            As[ac4 + 3][ar] = av.w;
        }
        // --- load B tile (pre-padded, fully coalesced)
        {
            float4 bv = *(const float4*)(g_WcatT + (size_t)(k0 + br) * NCAT + n0 + bc);
            *(float4*)&Bs[br][bc] = bv;
        }
        __syncthreads();

#pragma unroll
        for (int k = 0; k < 8; k++) {
            float4 a0 = *(const float4*)&As[k][ty * 8];
            float4 a1 = *(const float4*)&As[k][ty * 8 + 4];
            double2 bd0 = *(const double2*)&Bs[k][tx * 8];
            double2 bd1 = *(const double2*)&Bs[k][tx * 8 + 4];
            unsigned long long bq[4];
            bq[0] = __double_as_longlong(bd0.x);
            bq[1] = __double_as_longlong(bd0.y);
            bq[2] = __double_as_longlong(bd1.x);
            bq[3] = __double_as_longlong(bd1.y);
            float av[8] = {a0.x, a0.y, a0.z, a0.w, a1.x, a1.y, a1.z, a1.w};
#pragma unroll
            for (int i = 0; i < 8; i++) {
                unsigned long long a2 = pack2(av[i], av[i]);
#pragma unroll
                for (int j = 0; j < 4; j++) acc2[i][j] = fma2(a2, bq[j], acc2[i][j]);
            }
        }
        __syncthreads();
    }

    // --- epilogue: add bias, store float4 x2 per row
    float4 bia0 = *(const float4*)(g_bcat + n0 + tx * 8);
    float4 bia1 = *(const float4*)(g_bcat + n0 + tx * 8 + 4);
#pragma unroll
    for (int i = 0; i < 8; i++) {
        size_t m = (size_t)(m0 + ty * 8 + i);
        float2 p0 = unpack2(acc2[i][0]);
        float2 p1 = unpack2(acc2[i][1]);
        float2 p2 = unpack2(acc2[i][2]);
        float2 p3 = unpack2(acc2[i][3]);
        float4 o0 = make_float4(p0.x + bia0.x, p0.y + bia0.y, p1.x + bia0.z, p1.y + bia0.w);
        float4 o1 = make_float4(p2.x + bia1.x, p2.y + bia1.y, p3.x + bia1.z, p3.y + bia1.w);
        *(float4*)&g_xp[m * NCAT + n0 + tx * 8] = o0;
        *(float4*)&g_xp[m * NCAT + n0 + tx * 8 + 4] = o1;
    }
}

// ---------------------------------------------------------------------------
// Kernel 2: fused bidirectional GRU scan.
// One block per batch element, 384 threads = {fwd, bwd} x 192 gates.
// W_hh row kept in registers as 32 packed f32x2; h broadcast from smem.
// Only h after step 1 and final h are written out (feat layout).
// ---------------------------------------------------------------------------
__global__ __launch_bounds__(384, 2) void scan_kernel(
    const float* __restrict__ Whhf, const float* __restrict__ Whhb,
    const float* __restrict__ bhhf, const float* __restrict__ bhhb) {
    __shared__ __align__(16) float h[2][H_];
    __shared__ float sgh[2 * G3];
    __shared__ float sxp[2 * G3];

    const int b = blockIdx.x;
    const int tid = threadIdx.x;
    const int dir = tid >= G3;       // 0 fwd, 1 bwd
    const int g = dir ? tid - G3 : tid;

    // load my W_hh row (64 floats -> 32 packed pairs in registers)
    unsigned long long w2[32];
    {
        const float2* Wr = (const float2*)((dir ? Whhb : Whhf) + g * H_);
#pragma unroll
        for (int k = 0; k < 32; k++) {
            float2 t = Wr[k];
            w2[k] = pack2(t.x, t.y);
        }
    }
    const float bhh = (dir ? bhhb : bhhf)[g];

    if (g < H_) h[dir][g] = 0.f;

    const float* xpb = g_xp + (size_t)b * (T_ * NCAT);
    // prefetch step 0 input projection (tid already carries the +192 bwd offset)
    float xpre = xpb[(size_t)(dir ? (T_ - 1) : 0) * NCAT + tid];
    __syncthreads();

    for (int s = 0; s < T_; s++) {
        // ---- gh = h @ W_hh^T + b_hh (packed) ----
        unsigned long long acc2 = pack2(bhh, 0.f);
        const ulonglong2* h2 = (const ulonglong2*)h[dir];
#pragma unroll
        for (int k = 0; k < 16; k++) {
            ulonglong2 hv = h2[k];                 // broadcast LDS.128
            acc2 = fma2(w2[2 * k], hv.x, acc2);
            acc2 = fma2(w2[2 * k + 1], hv.y, acc2);
        }
        float2 pa = unpack2(acc2);
        sgh[tid] = pa.x + pa.y;
        sxp[tid] = xpre;
        if (s < T_ - 1)
            xpre = xpb[(size_t)(dir ? (T_ - 2 - s) : (s + 1)) * NCAT + tid];
        __syncthreads();

        // ---- gate combine + state update (first 64 lanes of each dir) ----
        if (g < H_) {
            int base = dir * G3;
            float r = sigmoidf_(sxp[base + g] + sgh[base + g]);
            float z = sigmoidf_(sxp[base + H_ + g] + sgh[base + H_ + g]);
            float n = tanhf_(sxp[base + 2 * H_ + g] + r * sgh[base + 2 * H_ + g]);
            float hold = h[dir][g];
            float hn = fmaf(z, hold - n, n);       // (1-z)*n + z*h
            h[dir][g] = hn;
            if (s == 0)
                g_feat[b * 256 + (dir ? 192 : 0) + g] = hn;    // hf1 | hb1
            if (s == T_ - 1)
                g_feat[b * 256 + (dir ? 64 : 128) + g] = hn;   // hbF | hfF
        }
        __syncthreads();
    }
}

// ---------------------------------------------------------------------------
// Kernel 3: head MLP  feat[256] -> 32 (LeakyReLU 0.01) -> 1
// one block (32 threads) per batch element
// ---------------------------------------------------------------------------
__global__ void head_kernel(const float* __restrict__ W1, const float* __restrict__ b1,
                            const float* __restrict__ W2, const float* __restrict__ b2,
                            float* __restrict__ out) {
    __shared__ float fs[256];
    const int b = blockIdx.x;
    const int j = threadIdx.x;     // 0..31
    for (int i = j; i < 256; i += 32) fs[i] = g_feat[b * 256 + i];
    __syncwarp();

    float acc = b1[j];
    const float* w = W1 + j * 256;
#pragma unroll 8
    for (int i = 0; i < 256; i++) acc = fmaf(fs[i], w[i], acc);
    acc = (acc >= 0.f) ? acc : 0.01f * acc;
    float v = acc * W2[j];
#pragma unroll
    for (int o = 16; o > 0; o >>= 1) v += __shfl_xor_sync(0xffffffff, v, o);
    if (j == 0) out[b] = v + b2[0];
}

// ---------------------------------------------------------------------------
extern "C" void kernel_launch(void* const* d_in, const int* in_sizes, int n_in,
                              void* d_out, int out_size) {
    const float* x    = (const float*)d_in[0];
    const float* Wif  = (const float*)d_in[1];
    const float* Whhf = (const float*)d_in[2];
    const float* bif  = (const float*)d_in[3];
    const float* bhhf = (const float*)d_in[4];
    const float* Wib  = (const float*)d_in[5];
    const float* Whhb = (const float*)d_in[6];
    const float* bib  = (const float*)d_in[7];
    const float* bhhb = (const float*)d_in[8];
    const float* W1   = (const float*)d_in[9];
    const float* b1   = (const float*)d_in[10];
    const float* W2   = (const float*)d_in[11];
    const float* b2   = (const float*)d_in[12];
    float* out = (float*)d_out;

    prep_kernel<<<(KPAD * NCAT + 255) / 256, 256>>>(Wif, Wib, bif, bib);

    dim3 ggrid(M_ / 128, NCAT / 128);
    gemm_kernel<<<ggrid, 256>>>(x);

    scan_kernel<<<B_, 384>>>(Whhf, Whhb, bhhf, bhhb);

    head_kernel<<<B_, 32>>>(W1, b1, W2, b2, out);
}

// round 3
// speedup vs baseline: 1.1874x; 1.1874x over previous
#include <cuda_runtime.h>
#include <cuda_bf16.h>
#include <cstdint>

// ---------------------------------------------------------------------------
// Problem constants
// ---------------------------------------------------------------------------
#define B_  256
#define T_  512
#define I_  300
#define H_  64
#define G3  192          // 3*H
#define NCAT 384         // 6*H
#define KP  320          // K padded (10 tiles of 32)
#define M_  (B_ * T_)    // 131072

#define BM 128
#define BN 128
#define BK 32
#define KTILES (KP / BK) // 10

// Scratch (static device memory; no allocation allowed)
__device__ float g_xp[(size_t)M_ * NCAT];         // ~201 MB
__device__ __nv_bfloat16 g_Wh[NCAT * KP];         // W hi, [n][k] K-major, padded
__device__ __nv_bfloat16 g_Wl[NCAT * KP];         // W lo
__device__ float g_bcat[NCAT];
__device__ float g_feat[B_ * 256];                // [b][ hf1 | hbF | hfF | hb1 ]

// ---------------------------------------------------------------------------
// MMA / ldmatrix helpers (baseline PTX, legal on sm_103 non-'a' target)
// ---------------------------------------------------------------------------
__device__ __forceinline__ uint32_t smem_u32(const void* p) {
    uint32_t a;
    asm("{ .reg .u64 t; cvta.to.shared.u64 t, %1; cvt.u32.u64 %0, t; }"
        : "=r"(a) : "l"(p));
    return a;
}
__device__ __forceinline__ void ldsm_x4(uint32_t addr, uint32_t& r0, uint32_t& r1,
                                        uint32_t& r2, uint32_t& r3) {
    asm volatile("ldmatrix.sync.aligned.m8n8.x4.shared.b16 {%0,%1,%2,%3}, [%4];"
                 : "=r"(r0), "=r"(r1), "=r"(r2), "=r"(r3) : "r"(addr));
}
__device__ __forceinline__ void mma16816(float* d, const uint32_t* a,
                                         uint32_t b0, uint32_t b1) {
    asm volatile(
        "mma.sync.aligned.m16n8k16.row.col.f32.bf16.bf16.f32 "
        "{%0,%1,%2,%3}, {%4,%5,%6,%7}, {%8,%9}, {%0,%1,%2,%3};"
        : "+f"(d[0]), "+f"(d[1]), "+f"(d[2]), "+f"(d[3])
        : "r"(a[0]), "r"(a[1]), "r"(a[2]), "r"(a[3]), "r"(b0), "r"(b1));
}

// swizzled byte offset within a [rows][32 bf16] tile (64B rows)
__device__ __forceinline__ uint32_t swz(int r, int u) {
    return (uint32_t)(r * 64 + ((u ^ ((r >> 1) & 3)) << 4));
}

// ---------------------------------------------------------------------------
// f32x2 packed helpers (for scan)
// ---------------------------------------------------------------------------
__device__ __forceinline__ unsigned long long pack2(float lo, float hi) {
    unsigned long long r;
    asm("mov.b64 %0, {%1, %2};" : "=l"(r) : "f"(lo), "f"(hi));
    return r;
}
__device__ __forceinline__ unsigned long long fma2(unsigned long long a,
                                                   unsigned long long b,
                                                   unsigned long long c) {
    unsigned long long d;
    asm("fma.rn.f32x2 %0, %1, %2, %3;" : "=l"(d) : "l"(a), "l"(b), "l"(c));
    return d;
}
__device__ __forceinline__ float2 unpack2(unsigned long long v) {
    float lo, hi;
    asm("mov.b64 {%0, %1}, %2;" : "=f"(lo), "=f"(hi) : "l"(v));
    return make_float2(lo, hi);
}
__device__ __forceinline__ float sigmoidf_(float x) {
    return __fdividef(1.f, 1.f + __expf(-x));
}
__device__ __forceinline__ float tanhf_(float x) {
    return 1.f - __fdividef(2.f, 1.f + __expf(2.f * x));
}

// ---------------------------------------------------------------------------
// Kernel 0: build bf16 hi/lo split of combined weight + bias
// ---------------------------------------------------------------------------
__global__ void prep_kernel(const float* __restrict__ Wif,
                            const float* __restrict__ Wib,
                            const float* __restrict__ bif,
                            const float* __restrict__ bib) {
    int i = blockIdx.x * blockDim.x + threadIdx.x;
    if (i < NCAT) g_bcat[i] = (i < G3) ? bif[i] : bib[i - G3];
    if (i < NCAT * KP) {
        int n = i / KP, k = i % KP;
        float v = 0.f;
        if (k < I_) v = (n < G3) ? Wif[n * I_ + k] : Wib[(n - G3) * I_ + k];
        __nv_bfloat16 h = __float2bfloat16(v);
        g_Wh[i] = h;
        g_Wl[i] = __float2bfloat16(v - __bfloat162float(h));
    }
}

// ---------------------------------------------------------------------------
// Kernel 1: HMMA bf16-split GEMM
//   xp[M,384] = x[M,300] @ Wcat[384,300]^T + bcat
//   D += Ahi*Bhi + Alo*Bhi + Ahi*Blo  (fp32 accumulators in registers)
//   CTA 128x128, BK=32, 8 warps (2M x 4N), warp tile 64x32
// ---------------------------------------------------------------------------
__global__ __launch_bounds__(256) void gemm_mma(const float* __restrict__ A) {
    __shared__ __align__(128) __nv_bfloat16 sAhi[BM * BK];
    __shared__ __align__(128) __nv_bfloat16 sAlo[BM * BK];
    __shared__ __align__(128) __nv_bfloat16 sBhi[BN * BK];
    __shared__ __align__(128) __nv_bfloat16 sBlo[BN * BK];

    const int tid = threadIdx.x;
    const int wid = tid >> 5;
    const int lid = tid & 31;
    const int m0 = blockIdx.x * BM;
    const int n0 = blockIdx.y * BN;

    const int wm = wid & 1;          // M half (0..1) -> rows wm*64
    const int wn = wid >> 1;         // N quarter (0..3) -> cols wn*32

    const uint32_t aHiB = smem_u32(sAhi);
    const uint32_t aLoB = smem_u32(sAlo);
    const uint32_t bHiB = smem_u32(sBhi);
    const uint32_t bLoB = smem_u32(sBlo);

    // ---- global load mapping ----
    const int ar = tid >> 1;             // A row 0..127
    const int ah = (tid & 1) * 16;       // A col half base
    const float* Arow = A + (size_t)(m0 + ar) * I_;

    const int br = tid >> 1;             // B row (n) 0..127
    const int bu = (tid & 1) * 2;        // B chunk base (16B chunks of 8 bf16)
    const __nv_bfloat16* BHrow = g_Wh + (size_t)(n0 + br) * KP;
    const __nv_bfloat16* BLrow = g_Wl + (size_t)(n0 + br) * KP;

    float4 va[4];
    uint4 vbh[2], vbl[2];

    // prefetch tile 0
    {
        const int k0 = 0;
#pragma unroll
        for (int j = 0; j < 4; j++) {
            int c = k0 + ah + j * 4;
            va[j] = (c < I_) ? *(const float4*)(Arow + c)
                             : make_float4(0.f, 0.f, 0.f, 0.f);
        }
#pragma unroll
        for (int j = 0; j < 2; j++) {
            vbh[j] = *(const uint4*)(BHrow + k0 + (bu + j) * 8);
            vbl[j] = *(const uint4*)(BLrow + k0 + (bu + j) * 8);
        }
    }

    float acc[4][4][4];
#pragma unroll
    for (int i = 0; i < 4; i++)
#pragma unroll
        for (int j = 0; j < 4; j++)
#pragma unroll
            for (int q = 0; q < 4; q++) acc[i][j][q] = 0.f;

    for (int t = 0; t < KTILES; t++) {
        // ---- store staged regs to smem (convert A to hi/lo) ----
#pragma unroll
        for (int j = 0; j < 4; j++) {
            int col = ah + j * 4;
            uint32_t off = swz(ar, col >> 3) + (col & 7) * 2;
            float fx = va[j].x, fy = va[j].y, fz = va[j].z, fw = va[j].w;
            __nv_bfloat16 h0 = __float2bfloat16(fx);
            __nv_bfloat16 h1 = __float2bfloat16(fy);
            __nv_bfloat16 h2 = __float2bfloat16(fz);
            __nv_bfloat16 h3 = __float2bfloat16(fw);
            __nv_bfloat16 l0 = __float2bfloat16(fx - __bfloat162float(h0));
            __nv_bfloat16 l1 = __float2bfloat16(fy - __bfloat162float(h1));
            __nv_bfloat16 l2 = __float2bfloat16(fz - __bfloat162float(h2));
            __nv_bfloat16 l3 = __float2bfloat16(fw - __bfloat162float(h3));
            __nv_bfloat162 hp0(h0, h1), hp1(h2, h3), lp0(l0, l1), lp1(l2, l3);
            *(uint2*)((char*)sAhi + off) =
                make_uint2(*(uint32_t*)&hp0, *(uint32_t*)&hp1);
            *(uint2*)((char*)sAlo + off) =
                make_uint2(*(uint32_t*)&lp0, *(uint32_t*)&lp1);
        }
#pragma unroll
        for (int j = 0; j < 2; j++) {
            uint32_t off = swz(br, bu + j);
            *(uint4*)((char*)sBhi + off) = vbh[j];
            *(uint4*)((char*)sBlo + off) = vbl[j];
        }
        __syncthreads();

        // ---- prefetch tile t+1 into regs (overlaps the MMAs below) ----
        if (t + 1 < KTILES) {
            const int k0 = (t + 1) * BK;
#pragma unroll
            for (int j = 0; j < 4; j++) {
                int c = k0 + ah + j * 4;
                va[j] = (c < I_) ? *(const float4*)(Arow + c)
                                 : make_float4(0.f, 0.f, 0.f, 0.f);
            }
#pragma unroll
            for (int j = 0; j < 2; j++) {
                vbh[j] = *(const uint4*)(BHrow + k0 + (bu + j) * 8);
                vbl[j] = *(const uint4*)(BLrow + k0 + (bu + j) * 8);
            }
        }

        // ---- compute: 2 k16 steps ----
#pragma unroll
        for (int s = 0; s < 2; s++) {
            uint32_t afh[4][4], afl[4][4], bfh[2][4], bfl[2][4];
            const int rA = (lid & 15);
            const int uu = s * 2 + (lid >> 4);
#pragma unroll
            for (int i = 0; i < 4; i++) {
                int r = wm * 64 + i * 16 + rA;
                uint32_t o = swz(r, uu);
                ldsm_x4(aHiB + o, afh[i][0], afh[i][1], afh[i][2], afh[i][3]);
                ldsm_x4(aLoB + o, afl[i][0], afl[i][1], afl[i][2], afl[i][3]);
            }
#pragma unroll
            for (int j2 = 0; j2 < 2; j2++) {
                int r = wn * 32 + j2 * 16 + rA;
                uint32_t o = swz(r, uu);
                ldsm_x4(bHiB + o, bfh[j2][0], bfh[j2][1], bfh[j2][2], bfh[j2][3]);
                ldsm_x4(bLoB + o, bfl[j2][0], bfl[j2][1], bfl[j2][2], bfl[j2][3]);
            }
#pragma unroll
            for (int i = 0; i < 4; i++) {
#pragma unroll
                for (int j2 = 0; j2 < 2; j2++) {
#pragma unroll
                    for (int g = 0; g < 2; g++) {
                        int j = j2 * 2 + g;
                        uint32_t h0 = bfh[j2][g], h1 = bfh[j2][g + 2];
                        uint32_t l0 = bfl[j2][g], l1 = bfl[j2][g + 2];
                        mma16816(acc[i][j], afh[i], h0, h1);   // hi*hi
                        mma16816(acc[i][j], afl[i], h0, h1);   // lo*hi
                        mma16816(acc[i][j], afh[i], l0, l1);   // hi*lo
                    }
                }
            }
        }
        __syncthreads();
    }

    // ---- epilogue: bias add + store ----
    const int erow = lid >> 2;
    const int ecol = (lid & 3) * 2;
#pragma unroll
    for (int i = 0; i < 4; i++) {
        int grow = m0 + wm * 64 + i * 16 + erow;
        float* out0 = g_xp + (size_t)grow * NCAT;
        float* out1 = g_xp + (size_t)(grow + 8) * NCAT;
#pragma unroll
        for (int j = 0; j < 4; j++) {
            int gcol = n0 + wn * 32 + j * 8 + ecol;
            float2 bi = *(const float2*)(g_bcat + gcol);
            *(float2*)(out0 + gcol) =
                make_float2(acc[i][j][0] + bi.x, acc[i][j][1] + bi.y);
            *(float2*)(out1 + gcol) =
                make_float2(acc[i][j][2] + bi.x, acc[i][j][3] + bi.y);
        }
    }
}

// ---------------------------------------------------------------------------
// Kernel 2: fused bidirectional GRU scan (R1-proven)
// ---------------------------------------------------------------------------
__global__ __launch_bounds__(384, 2) void scan_kernel(
    const float* __restrict__ Whhf, const float* __restrict__ Whhb,
    const float* __restrict__ bhhf, const float* __restrict__ bhhb) {
    __shared__ __align__(16) float h[2][H_];
    __shared__ float sgh[2 * G3];
    __shared__ float sxp[2 * G3];

    const int b = blockIdx.x;
    const int tid = threadIdx.x;
    const int dir = tid >= G3;
    const int g = dir ? tid - G3 : tid;

    unsigned long long w2[32];
    {
        const float2* Wr = (const float2*)((dir ? Whhb : Whhf) + g * H_);
#pragma unroll
        for (int k = 0; k < 32; k++) {
            float2 t = Wr[k];
            w2[k] = pack2(t.x, t.y);
        }
    }
    const float bhh = (dir ? bhhb : bhhf)[g];

    if (g < H_) h[dir][g] = 0.f;

    const float* xpb = g_xp + (size_t)b * (T_ * NCAT);
    float xpre = xpb[(size_t)(dir ? (T_ - 1) : 0) * NCAT + tid];
    __syncthreads();

    for (int s = 0; s < T_; s++) {
        unsigned long long acc2 = pack2(bhh, 0.f);
        unsigned long long acc2b = pack2(0.f, 0.f);
        const ulonglong2* h2 = (const ulonglong2*)h[dir];
#pragma unroll
        for (int k = 0; k < 16; k++) {
            ulonglong2 hv = h2[k];
            acc2 = fma2(w2[2 * k], hv.x, acc2);
            acc2b = fma2(w2[2 * k + 1], hv.y, acc2b);
        }
        float2 pa = unpack2(acc2);
        float2 pb = unpack2(acc2b);
        sgh[tid] = (pa.x + pa.y) + (pb.x + pb.y);
        sxp[tid] = xpre;
        if (s < T_ - 1)
            xpre = xpb[(size_t)(dir ? (T_ - 2 - s) : (s + 1)) * NCAT + tid];
        __syncthreads();

        if (g < H_) {
            int base = dir * G3;
            float r = sigmoidf_(sxp[base + g] + sgh[base + g]);
            float z = sigmoidf_(sxp[base + H_ + g] + sgh[base + H_ + g]);
            float n = tanhf_(sxp[base + 2 * H_ + g] + r * sgh[base + 2 * H_ + g]);
            float hold = h[dir][g];
            float hn = fmaf(z, hold - n, n);
            h[dir][g] = hn;
            if (s == 0)
                g_feat[b * 256 + (dir ? 192 : 0) + g] = hn;
            if (s == T_ - 1)
                g_feat[b * 256 + (dir ? 64 : 128) + g] = hn;
        }
        __syncthreads();
    }
}

// ---------------------------------------------------------------------------
// Kernel 3: head MLP  feat[256] -> 32 (LeakyReLU) -> 1, 256 thr/block
// ---------------------------------------------------------------------------
__global__ __launch_bounds__(256) void head_kernel(
    const float* __restrict__ W1, const float* __restrict__ b1,
    const float* __restrict__ W2, const float* __restrict__ b2,
    float* __restrict__ out) {
    __shared__ float fs[256];
    __shared__ float hs[32];
    const int b = blockIdx.x;
    const int tid = threadIdx.x;
    fs[tid] = g_feat[b * 256 + tid];
    __syncthreads();

    const int j = tid >> 3, p = tid & 7;
    const float* w = W1 + j * 256 + p * 32;
    const float* f = fs + p * 32;
    float acc = 0.f;
#pragma unroll
    for (int i = 0; i < 32; i++) acc = fmaf(f[i], w[i], acc);
    acc += __shfl_xor_sync(0xffffffffu, acc, 1);
    acc += __shfl_xor_sync(0xffffffffu, acc, 2);
    acc += __shfl_xor_sync(0xffffffffu, acc, 4);
    if (p == 0) {
        float hv = acc + b1[j];
        hv = (hv >= 0.f) ? hv : 0.01f * hv;
        hs[j] = hv * W2[j];
    }
    __syncthreads();
    if (tid < 32) {
        float v = hs[tid];
#pragma unroll
        for (int o = 16; o > 0; o >>= 1) v += __shfl_xor_sync(0xffffffffu, v, o);
        if (tid == 0) out[b] = v + b2[0];
    }
}

// ---------------------------------------------------------------------------
extern "C" void kernel_launch(void* const* d_in, const int* in_sizes, int n_in,
                              void* d_out, int out_size) {
    const float* x    = (const float*)d_in[0];
    const float* Wif  = (const float*)d_in[1];
    const float* Whhf = (const float*)d_in[2];
    const float* bif  = (const float*)d_in[3];
    const float* bhhf = (const float*)d_in[4];
    const float* Wib  = (const float*)d_in[5];
    const float* Whhb = (const float*)d_in[6];
    const float* bib  = (const float*)d_in[7];
    const float* bhhb = (const float*)d_in[8];
    const float* W1   = (const float*)d_in[9];
    const float* b1   = (const float*)d_in[10];
    const float* W2   = (const float*)d_in[11];
    const float* b2   = (const float*)d_in[12];
    float* out = (float*)d_out;

    prep_kernel<<<(NCAT * KP + 255) / 256, 256>>>(Wif, Wib, bif, bib);

    dim3 ggrid(M_ / BM, NCAT / BN);
    gemm_mma<<<ggrid, 256>>>(x);

    scan_kernel<<<B_, 384>>>(Whhf, Whhb, bhhf, bhhb);

    head_kernel<<<B_, 256>>>(W1, b1, W2, b2, out);
}